// round 2
// baseline (speedup 1.0000x reference)
#include <cuda_runtime.h>
#include <math.h>

// 0: x        [1024, 2560] f32
// 1: h        [1024, 2560, 16] f32
// 2: W_dt_low [160, 2560] f32
// 3: W_dt     [2560, 160] f32
// 4: b_dt     [2560] f32
// 5: W_B      [16, 2560] f32
// 6: W_C      [16, 2560] f32
// 7: A_log    [2560, 16] f32
// 8: D        [2560] f32
// out: y      [1024, 2560] f32

#define B_SZ    1024
#define DIN     2560
#define DST     16
#define DTR     160
#define NPROJ   192      // 160 (dt_low) + 16 (Bt) + 16 (Ct)
#define SPLITK  8
#define KSPLIT  (DIN / SPLITK)   // 320

// ---------------- device scratch ----------------
__device__ __align__(16) float g_partial[SPLITK * B_SZ * NPROJ];
__device__ __align__(16) float g_proj[B_SZ * NPROJ];              // dt_low | Bt | Ct
__device__ __align__(16) float g_A2[DIN * DST];                   // -exp(A_log)

// ---------------- A2 = -exp(A_log) ----------------
__global__ void prep_a_kernel(const float* __restrict__ a_log) {
    int i = blockIdx.x * blockDim.x + threadIdx.x;
    if (i < DIN * DST) g_A2[i] = -__expf(a_log[i]);
}

// ---------------- GEMM1 (split-K): partial[z] = x[64,320] @ W[64,320]^T ----------------
// Weight rows selected directly from the three source matrices (no pack pass).
__global__ __launch_bounds__(256) void gemm1_kernel(const float* __restrict__ x,
                                                    const float* __restrict__ wdtlow,
                                                    const float* __restrict__ wb,
                                                    const float* __restrict__ wc) {
    __shared__ float As[16][68];
    __shared__ float Bs[16][68];
    const int tid = threadIdx.x;
    const int mBase = blockIdx.x * 64;
    const int nBase = blockIdx.y * 64;
    const int k0 = blockIdx.z * KSPLIT;
    const int tm = tid >> 4;
    const int tn = tid & 15;
    const int lr = tid >> 2;
    const int lk = (tid & 3) * 4;

    // per-row weight source selection
    const int wr = nBase + lr;
    const float* wrow;
    if (wr < DTR)            wrow = wdtlow + (size_t)wr * DIN;
    else if (wr < DTR + DST) wrow = wb + (size_t)(wr - DTR) * DIN;
    else                     wrow = wc + (size_t)(wr - DTR - DST) * DIN;

    float c[4][4] = {};
    const float* aptr = x    + (size_t)(mBase + lr) * DIN + k0 + lk;
    const float* bptr = wrow + k0 + lk;

    for (int kt = 0; kt < KSPLIT; kt += 16) {
        float4 av = *reinterpret_cast<const float4*>(aptr + kt);
        float4 bv = *reinterpret_cast<const float4*>(bptr + kt);
        As[lk + 0][lr] = av.x; As[lk + 1][lr] = av.y;
        As[lk + 2][lr] = av.z; As[lk + 3][lr] = av.w;
        Bs[lk + 0][lr] = bv.x; Bs[lk + 1][lr] = bv.y;
        Bs[lk + 2][lr] = bv.z; Bs[lk + 3][lr] = bv.w;
        __syncthreads();
#pragma unroll
        for (int kk = 0; kk < 16; kk++) {
            float4 a = *reinterpret_cast<const float4*>(&As[kk][tm * 4]);
            float4 b = *reinterpret_cast<const float4*>(&Bs[kk][tn * 4]);
            c[0][0] = fmaf(a.x, b.x, c[0][0]); c[0][1] = fmaf(a.x, b.y, c[0][1]);
            c[0][2] = fmaf(a.x, b.z, c[0][2]); c[0][3] = fmaf(a.x, b.w, c[0][3]);
            c[1][0] = fmaf(a.y, b.x, c[1][0]); c[1][1] = fmaf(a.y, b.y, c[1][1]);
            c[1][2] = fmaf(a.y, b.z, c[1][2]); c[1][3] = fmaf(a.y, b.w, c[1][3]);
            c[2][0] = fmaf(a.z, b.x, c[2][0]); c[2][1] = fmaf(a.z, b.y, c[2][1]);
            c[2][2] = fmaf(a.z, b.z, c[2][2]); c[2][3] = fmaf(a.z, b.w, c[2][3]);
            c[3][0] = fmaf(a.w, b.x, c[3][0]); c[3][1] = fmaf(a.w, b.y, c[3][1]);
            c[3][2] = fmaf(a.w, b.z, c[3][2]); c[3][3] = fmaf(a.w, b.w, c[3][3]);
        }
        __syncthreads();
    }
    float* out = g_partial + ((size_t)blockIdx.z * B_SZ + mBase) * NPROJ + nBase;
#pragma unroll
    for (int i = 0; i < 4; i++) {
        float4 v = make_float4(c[i][0], c[i][1], c[i][2], c[i][3]);
        *reinterpret_cast<float4*>(out + (size_t)(tm * 4 + i) * NPROJ + tn * 4) = v;
    }
}

// ---------------- split-K reduce (float2 granularity, 2x parallelism) ----------------
__global__ void reduce_kernel() {
    int i = blockIdx.x * blockDim.x + threadIdx.x;
    const int total2 = B_SZ * NPROJ / 2;
    if (i >= total2) return;
    const float2* p = reinterpret_cast<const float2*>(g_partial);
    float2 s = p[i];
#pragma unroll
    for (int z = 1; z < SPLITK; z++) {
        float2 v = p[(size_t)z * total2 + i];
        s.x += v.x; s.y += v.y;
    }
    reinterpret_cast<float2*>(g_proj)[i] = s;
}

// ---------------- fused GEMM2 + softplus + SSM ----------------
// dt[b,d] = softplus(proj[b,0:160] . W_dt[d,:] + b_dt[d])
// y[b,d]  = sum_n (exp(dt*A[d,n])*h[b,d,n] + dt*Bt[b,n]*x[b,d]) * Ct[b,n] + D[d]*x[b,d]
__global__ __launch_bounds__(256) void fused_kernel(const float* __restrict__ wdt,
                                                    const float* __restrict__ bdt,
                                                    const float* __restrict__ x,
                                                    const float* __restrict__ h,
                                                    const float* __restrict__ Dv,
                                                    float* __restrict__ y) {
    __shared__ float As[16][68];
    __shared__ float Bs[16][68];
    __shared__ float BC[64][32];   // Bt(16) | Ct(16) per local batch row
    __shared__ float A2s[64][16];  // -exp(A_log) per local d row
    __shared__ float Dvs[64];

    const int tid = threadIdx.x;
    const int mBase = blockIdx.x * 64;   // batch
    const int nBase = blockIdx.y * 64;   // d_inner
    const int tm = tid >> 4;
    const int tn = tid & 15;
    const int lr = tid >> 2;
    const int lk = (tid & 3) * 4;

    // stage Bt/Ct: proj[b, 160:192], 64 rows x 8 float4
    {
        int t0 = tid;                   // 0..255 -> 512 float4 in 2 steps
#pragma unroll
        for (int s = 0; s < 2; s++) {
            int t = t0 + s * 256;
            int row = t >> 3;
            int col = (t & 7) * 4;
            *reinterpret_cast<float4*>(&BC[row][col]) =
                *reinterpret_cast<const float4*>(g_proj + (size_t)(mBase + row) * NPROJ + DTR + col);
        }
        // A2: 64 rows x 4 float4 = 256 float4
        int row = tid >> 2;
        int col = (tid & 3) * 4;
        *reinterpret_cast<float4*>(&A2s[row][col]) =
            *reinterpret_cast<const float4*>(g_A2 + (size_t)(nBase + row) * DST + col);
        if (tid < 64) Dvs[tid] = Dv[nBase + tid];
    }

    float c[4][4] = {};
    const float* aptr = g_proj + (size_t)(mBase + lr) * NPROJ + lk;
    const float* bptr = wdt    + (size_t)(nBase + lr) * DTR + lk;

    for (int kt = 0; kt < DTR; kt += 16) {
        float4 av = *reinterpret_cast<const float4*>(aptr + kt);
        float4 bv = *reinterpret_cast<const float4*>(bptr + kt);
        As[lk + 0][lr] = av.x; As[lk + 1][lr] = av.y;
        As[lk + 2][lr] = av.z; As[lk + 3][lr] = av.w;
        Bs[lk + 0][lr] = bv.x; Bs[lk + 1][lr] = bv.y;
        Bs[lk + 2][lr] = bv.z; Bs[lk + 3][lr] = bv.w;
        __syncthreads();
#pragma unroll
        for (int kk = 0; kk < 16; kk++) {
            float4 a = *reinterpret_cast<const float4*>(&As[kk][tm * 4]);
            float4 b = *reinterpret_cast<const float4*>(&Bs[kk][tn * 4]);
            c[0][0] = fmaf(a.x, b.x, c[0][0]); c[0][1] = fmaf(a.x, b.y, c[0][1]);
            c[0][2] = fmaf(a.x, b.z, c[0][2]); c[0][3] = fmaf(a.x, b.w, c[0][3]);
            c[1][0] = fmaf(a.y, b.x, c[1][0]); c[1][1] = fmaf(a.y, b.y, c[1][1]);
            c[1][2] = fmaf(a.y, b.z, c[1][2]); c[1][3] = fmaf(a.y, b.w, c[1][3]);
            c[2][0] = fmaf(a.z, b.x, c[2][0]); c[2][1] = fmaf(a.z, b.y, c[2][1]);
            c[2][2] = fmaf(a.z, b.z, c[2][2]); c[2][3] = fmaf(a.z, b.w, c[2][3]);
            c[3][0] = fmaf(a.w, b.x, c[3][0]); c[3][1] = fmaf(a.w, b.y, c[3][1]);
            c[3][2] = fmaf(a.w, b.z, c[3][2]); c[3][3] = fmaf(a.w, b.w, c[3][3]);
        }
        __syncthreads();
    }

    // ---- fused epilogue: softplus + selective-scan step + output ----
    const int d0 = nBase + tn * 4;         // 4 contiguous d's
    const int dl = tn * 4;                 // local d
    float4 bb = *reinterpret_cast<const float4*>(bdt + d0);
    float4 D4 = *reinterpret_cast<const float4*>(&Dvs[dl]);

#pragma unroll
    for (int i = 0; i < 4; i++) {
        const int bl = tm * 4 + i;
        const int b = mBase + bl;
        // softplus(dt) for the 4 d's of this row
        float dt_[4];
        {
            float z0 = c[i][0] + bb.x, z1 = c[i][1] + bb.y;
            float z2 = c[i][2] + bb.z, z3 = c[i][3] + bb.w;
            dt_[0] = fmaxf(z0, 0.f) + log1pf(__expf(-fabsf(z0)));
            dt_[1] = fmaxf(z1, 0.f) + log1pf(__expf(-fabsf(z1)));
            dt_[2] = fmaxf(z2, 0.f) + log1pf(__expf(-fabsf(z2)));
            dt_[3] = fmaxf(z3, 0.f) + log1pf(__expf(-fabsf(z3)));
        }
        float4 xv = *reinterpret_cast<const float4*>(x + (size_t)b * DIN + d0);
        const float xval[4] = {xv.x, xv.y, xv.z, xv.w};
        const float Dval[4] = {D4.x, D4.y, D4.z, D4.w};
        float4 yv;
        float* yp = &yv.x;
#pragma unroll
        for (int j = 0; j < 4; j++) {
            const float dtv = dt_[j];
            const float dx = dtv * xval[j];
            const float* hrow = h + ((size_t)b * DIN + (d0 + j)) * DST;
            const float* arow = &A2s[dl + j][0];
            float acc = 0.f;
#pragma unroll
            for (int q = 0; q < 4; q++) {
                float4 h4 = *reinterpret_cast<const float4*>(hrow + q * 4);
                float4 A4 = *reinterpret_cast<const float4*>(arow + q * 4);
                float4 B4 = *reinterpret_cast<const float4*>(&BC[bl][q * 4]);
                float4 C4 = *reinterpret_cast<const float4*>(&BC[bl][16 + q * 4]);
                float e0 = __expf(dtv * A4.x);
                float e1 = __expf(dtv * A4.y);
                float e2 = __expf(dtv * A4.z);
                float e3 = __expf(dtv * A4.w);
                float hn0 = fmaf(e0, h4.x, dx * B4.x);
                float hn1 = fmaf(e1, h4.y, dx * B4.y);
                float hn2 = fmaf(e2, h4.z, dx * B4.z);
                float hn3 = fmaf(e3, h4.w, dx * B4.w);
                acc = fmaf(hn0, C4.x, acc);
                acc = fmaf(hn1, C4.y, acc);
                acc = fmaf(hn2, C4.z, acc);
                acc = fmaf(hn3, C4.w, acc);
            }
            yp[j] = fmaf(Dval[j], xval[j], acc);
        }
        *reinterpret_cast<float4*>(y + (size_t)b * DIN + d0) = yv;
    }
}

// ---------------- launch ----------------
extern "C" void kernel_launch(void* const* d_in, const int* in_sizes, int n_in,
                              void* d_out, int out_size) {
    const float* x       = (const float*)d_in[0];
    const float* h       = (const float*)d_in[1];
    const float* wdtlow  = (const float*)d_in[2];
    const float* wdt     = (const float*)d_in[3];
    const float* bdt     = (const float*)d_in[4];
    const float* wb      = (const float*)d_in[5];
    const float* wc      = (const float*)d_in[6];
    const float* alog    = (const float*)d_in[7];
    const float* Dv      = (const float*)d_in[8];
    float* y = (float*)d_out;

    prep_a_kernel<<<(DIN * DST + 255) / 256, 256>>>(alog);
    gemm1_kernel<<<dim3(B_SZ / 64, NPROJ / 64, SPLITK), 256>>>(x, wdtlow, wb, wc);
    reduce_kernel<<<(B_SZ * NPROJ / 2 + 255) / 256, 256>>>();
    fused_kernel<<<dim3(B_SZ / 64, DIN / 64), 256>>>(wdt, bdt, x, h, Dv, y);
}

// round 3
// speedup vs baseline: 1.0090x; 1.0090x over previous
#include <cuda_runtime.h>
#include <math.h>

// 0: x [1024,2560]  1: h [1024,2560,16]  2: W_dt_low [160,2560]  3: W_dt [2560,160]
// 4: b_dt [2560]    5: W_B [16,2560]     6: W_C [16,2560]        7: A_log [2560,16]
// 8: D [2560]       out: y [1024,2560]   all f32

#define B_SZ    1024
#define DIN     2560
#define DST     16
#define DTR     160
#define NPROJ   192
#define SPLITK  16
#define KSPLIT  (DIN / SPLITK)   // 160

typedef unsigned long long u64;

// ---------------- device scratch ----------------
__device__ __align__(16) float g_partial[SPLITK * B_SZ * NPROJ];  // 12.6 MB
__device__ __align__(16) float g_proj[B_SZ * NPROJ];              // dt_low | Bt | Ct
__device__ __align__(16) float g_dt[B_SZ * DIN];
__device__ __align__(16) float g_A2[DIN * DST];

// ---------------- packed fp32x2 helpers ----------------
__device__ __forceinline__ u64 pk2(float lo, float hi) {
    u64 r; asm("mov.b64 %0, {%1, %2};" : "=l"(r) : "f"(lo), "f"(hi)); return r;
}
__device__ __forceinline__ void fma2(u64& c, u64 a, u64 b) {
    asm("fma.rn.f32x2 %0, %1, %2, %0;" : "+l"(c) : "l"(a), "l"(b));
}
__device__ __forceinline__ float2 upk2(u64 v) {
    float2 f; asm("mov.b64 {%0, %1}, %2;" : "=f"(f.x), "=f"(f.y) : "l"(v)); return f;
}

// ---------------- A2 = -exp(A_log) ----------------
__global__ void prep_a_kernel(const float* __restrict__ a_log) {
    int i = blockIdx.x * blockDim.x + threadIdx.x;
    if (i < DIN * DST) g_A2[i] = -__expf(a_log[i]);
}

// ---------------- GEMM1 (split-K): 64m x 64n tile, 128 thr, microtile 4x8 ----------------
// partial[z][m, n] = sum_{k in slice z} x[m,k] * W[n,k]
__global__ __launch_bounds__(128) void gemm1_kernel(const float* __restrict__ x,
                                                    const float* __restrict__ wdtlow,
                                                    const float* __restrict__ wb,
                                                    const float* __restrict__ wc) {
    __shared__ float As[16][72];   // [k][m]
    __shared__ float Bs[16][72];   // [k][n]
    const int tid = threadIdx.x;
    const int mBase = blockIdx.x * 64;
    const int nBase = blockIdx.y * 64;
    const int k0 = blockIdx.z * KSPLIT;
    const int tm = tid >> 3;          // 0..15 -> m quad
    const int tn = tid & 7;           // 0..7  -> n oct
    const int lr = tid >> 2;          // 0..31 load row
    const int lk = (tid & 3) * 4;

    // weight row sources for the two B-load rows
    const int wr0 = nBase + lr, wr1 = nBase + lr + 32;
    const float* wrow0 = (wr0 < DTR) ? wdtlow + (size_t)wr0 * DIN
                      : (wr0 < DTR + DST) ? wb + (size_t)(wr0 - DTR) * DIN
                      : wc + (size_t)(wr0 - DTR - DST) * DIN;
    const float* wrow1 = (wr1 < DTR) ? wdtlow + (size_t)wr1 * DIN
                      : (wr1 < DTR + DST) ? wb + (size_t)(wr1 - DTR) * DIN
                      : wc + (size_t)(wr1 - DTR - DST) * DIN;

    u64 c[4][4] = {};   // [m][n-pair]
    const float* a0 = x + (size_t)(mBase + lr) * DIN + k0 + lk;
    const float* a1 = x + (size_t)(mBase + lr + 32) * DIN + k0 + lk;

    for (int kt = 0; kt < KSPLIT; kt += 16) {
        float4 av0 = *reinterpret_cast<const float4*>(a0 + kt);
        float4 av1 = *reinterpret_cast<const float4*>(a1 + kt);
        float4 bv0 = *reinterpret_cast<const float4*>(wrow0 + k0 + kt + lk);
        float4 bv1 = *reinterpret_cast<const float4*>(wrow1 + k0 + kt + lk);
        As[lk + 0][lr] = av0.x; As[lk + 1][lr] = av0.y; As[lk + 2][lr] = av0.z; As[lk + 3][lr] = av0.w;
        As[lk + 0][lr + 32] = av1.x; As[lk + 1][lr + 32] = av1.y; As[lk + 2][lr + 32] = av1.z; As[lk + 3][lr + 32] = av1.w;
        Bs[lk + 0][lr] = bv0.x; Bs[lk + 1][lr] = bv0.y; Bs[lk + 2][lr] = bv0.z; Bs[lk + 3][lr] = bv0.w;
        Bs[lk + 0][lr + 32] = bv1.x; Bs[lk + 1][lr + 32] = bv1.y; Bs[lk + 2][lr + 32] = bv1.z; Bs[lk + 3][lr + 32] = bv1.w;
        __syncthreads();
#pragma unroll
        for (int kk = 0; kk < 16; kk++) {
            float4 a = *reinterpret_cast<const float4*>(&As[kk][tm * 4]);
            ulonglong2 b01 = *reinterpret_cast<const ulonglong2*>(&Bs[kk][tn * 8]);
            ulonglong2 b23 = *reinterpret_cast<const ulonglong2*>(&Bs[kk][tn * 8 + 4]);
            u64 ad0 = pk2(a.x, a.x), ad1 = pk2(a.y, a.y);
            u64 ad2 = pk2(a.z, a.z), ad3 = pk2(a.w, a.w);
            fma2(c[0][0], ad0, b01.x); fma2(c[0][1], ad0, b01.y); fma2(c[0][2], ad0, b23.x); fma2(c[0][3], ad0, b23.y);
            fma2(c[1][0], ad1, b01.x); fma2(c[1][1], ad1, b01.y); fma2(c[1][2], ad1, b23.x); fma2(c[1][3], ad1, b23.y);
            fma2(c[2][0], ad2, b01.x); fma2(c[2][1], ad2, b01.y); fma2(c[2][2], ad2, b23.x); fma2(c[2][3], ad2, b23.y);
            fma2(c[3][0], ad3, b01.x); fma2(c[3][1], ad3, b01.y); fma2(c[3][2], ad3, b23.x); fma2(c[3][3], ad3, b23.y);
        }
        __syncthreads();
    }
    float* out = g_partial + ((size_t)blockIdx.z * B_SZ + mBase) * NPROJ + nBase + tn * 8;
#pragma unroll
    for (int i = 0; i < 4; i++) {
        float2 p0 = upk2(c[i][0]), p1 = upk2(c[i][1]), p2 = upk2(c[i][2]), p3 = upk2(c[i][3]);
        float* row = out + (size_t)(tm * 4 + i) * NPROJ;
        *reinterpret_cast<float4*>(row)     = make_float4(p0.x, p0.y, p1.x, p1.y);
        *reinterpret_cast<float4*>(row + 4) = make_float4(p2.x, p2.y, p3.x, p3.y);
    }
}

// ---------------- split-K reduce (float2) ----------------
__global__ void reduce_kernel() {
    int i = blockIdx.x * blockDim.x + threadIdx.x;
    const int total2 = B_SZ * NPROJ / 2;
    if (i >= total2) return;
    const float2* p = reinterpret_cast<const float2*>(g_partial);
    float2 s = p[i];
#pragma unroll
    for (int z = 1; z < SPLITK; z++) {
        float2 v = p[(size_t)z * total2 + i];
        s.x += v.x; s.y += v.y;
    }
    reinterpret_cast<float2*>(g_proj)[i] = s;
}

// ---------------- GEMM2 + softplus: 128m x 64n tile, 256 thr, microtile 4x8 ----------------
__global__ __launch_bounds__(256) void gemm2_kernel(const float* __restrict__ wdt,
                                                    const float* __restrict__ bdt) {
    __shared__ float As[16][136];  // [k][m], m tile = 128
    __shared__ float Bs[16][72];   // [k][n]
    const int tid = threadIdx.x;
    const int mBase = blockIdx.x * 128;
    const int nBase = blockIdx.y * 64;
    const int tm = tid >> 3;          // 0..31
    const int tn = tid & 7;           // 0..7
    const int lr = tid >> 2;          // 0..63
    const int lk = (tid & 3) * 4;

    u64 c[4][4] = {};
    const float* a0 = g_proj + (size_t)(mBase + lr) * NPROJ + lk;
    const float* a1 = g_proj + (size_t)(mBase + lr + 64) * NPROJ + lk;
    const float* b0 = wdt + (size_t)(nBase + lr) * DTR + lk;

    for (int kt = 0; kt < DTR; kt += 16) {
        float4 av0 = *reinterpret_cast<const float4*>(a0 + kt);
        float4 av1 = *reinterpret_cast<const float4*>(a1 + kt);
        float4 bv  = *reinterpret_cast<const float4*>(b0 + kt);
        As[lk + 0][lr] = av0.x; As[lk + 1][lr] = av0.y; As[lk + 2][lr] = av0.z; As[lk + 3][lr] = av0.w;
        As[lk + 0][lr + 64] = av1.x; As[lk + 1][lr + 64] = av1.y; As[lk + 2][lr + 64] = av1.z; As[lk + 3][lr + 64] = av1.w;
        Bs[lk + 0][lr] = bv.x; Bs[lk + 1][lr] = bv.y; Bs[lk + 2][lr] = bv.z; Bs[lk + 3][lr] = bv.w;
        __syncthreads();
#pragma unroll
        for (int kk = 0; kk < 16; kk++) {
            float4 a = *reinterpret_cast<const float4*>(&As[kk][tm * 4]);
            ulonglong2 b01 = *reinterpret_cast<const ulonglong2*>(&Bs[kk][tn * 8]);
            ulonglong2 b23 = *reinterpret_cast<const ulonglong2*>(&Bs[kk][tn * 8 + 4]);
            u64 ad0 = pk2(a.x, a.x), ad1 = pk2(a.y, a.y);
            u64 ad2 = pk2(a.z, a.z), ad3 = pk2(a.w, a.w);
            fma2(c[0][0], ad0, b01.x); fma2(c[0][1], ad0, b01.y); fma2(c[0][2], ad0, b23.x); fma2(c[0][3], ad0, b23.y);
            fma2(c[1][0], ad1, b01.x); fma2(c[1][1], ad1, b01.y); fma2(c[1][2], ad1, b23.x); fma2(c[1][3], ad1, b23.y);
            fma2(c[2][0], ad2, b01.x); fma2(c[2][1], ad2, b01.y); fma2(c[2][2], ad2, b23.x); fma2(c[2][3], ad2, b23.y);
            fma2(c[3][0], ad3, b01.x); fma2(c[3][1], ad3, b01.y); fma2(c[3][2], ad3, b23.x); fma2(c[3][3], ad3, b23.y);
        }
        __syncthreads();
    }
    // softplus epilogue
    const int gn = nBase + tn * 8;
    float4 bb0 = *reinterpret_cast<const float4*>(bdt + gn);
    float4 bb1 = *reinterpret_cast<const float4*>(bdt + gn + 4);
#pragma unroll
    for (int i = 0; i < 4; i++) {
        float2 p0 = upk2(c[i][0]), p1 = upk2(c[i][1]), p2 = upk2(c[i][2]), p3 = upk2(c[i][3]);
        float zv[8] = {p0.x + bb0.x, p0.y + bb0.y, p1.x + bb0.z, p1.y + bb0.w,
                       p2.x + bb1.x, p2.y + bb1.y, p3.x + bb1.z, p3.y + bb1.w};
        float sp[8];
#pragma unroll
        for (int j = 0; j < 8; j++)
            sp[j] = fmaxf(zv[j], 0.f) + log1pf(__expf(-fabsf(zv[j])));
        float* row = g_dt + (size_t)(mBase + tm * 4 + i) * DIN + gn;
        *reinterpret_cast<float4*>(row)     = make_float4(sp[0], sp[1], sp[2], sp[3]);
        *reinterpret_cast<float4*>(row + 4) = make_float4(sp[4], sp[5], sp[6], sp[7]);
    }
}

// ---------------- elementwise SSM (round-1 layout: coalesced h) ----------------
__global__ __launch_bounds__(256) void ssm_kernel(const float* __restrict__ x,
                                                  const float* __restrict__ h,
                                                  const float* __restrict__ Dv,
                                                  float* __restrict__ y) {
    __shared__ float ys[64];
    const int b = blockIdx.y;
    const int dBase = blockIdx.x * 64;
    const int tid = threadIdx.x;
    const int l4 = tid & 3;
    const int d = dBase + (tid >> 2);
    const int pair = b * DIN + d;

    const float dt_v = g_dt[pair];
    const float x_v = x[pair];
    const float4 h4  = *reinterpret_cast<const float4*>(h + (size_t)pair * DST + l4 * 4);
    const float4 A4  = *reinterpret_cast<const float4*>(g_A2 + (size_t)d * DST + l4 * 4);
    const float4 Bt4 = *reinterpret_cast<const float4*>(g_proj + (size_t)b * NPROJ + DTR + l4 * 4);
    const float4 Ct4 = *reinterpret_cast<const float4*>(g_proj + (size_t)b * NPROJ + DTR + DST + l4 * 4);

    const float dx = dt_v * x_v;
    float acc;
    {
        float e0 = __expf(dt_v * A4.x);
        float e1 = __expf(dt_v * A4.y);
        float e2 = __expf(dt_v * A4.z);
        float e3 = __expf(dt_v * A4.w);
        float hn0 = fmaf(e0, h4.x, dx * Bt4.x);
        float hn1 = fmaf(e1, h4.y, dx * Bt4.y);
        float hn2 = fmaf(e2, h4.z, dx * Bt4.z);
        float hn3 = fmaf(e3, h4.w, dx * Bt4.w);
        acc = hn0 * Ct4.x;
        acc = fmaf(hn1, Ct4.y, acc);
        acc = fmaf(hn2, Ct4.z, acc);
        acc = fmaf(hn3, Ct4.w, acc);
    }
    acc += __shfl_xor_sync(0xffffffffu, acc, 1);
    acc += __shfl_xor_sync(0xffffffffu, acc, 2);
    if (l4 == 0) ys[tid >> 2] = fmaf(Dv[d], x_v, acc);
    __syncthreads();
    if (tid < 64) y[(size_t)b * DIN + dBase + tid] = ys[tid];
}

// ---------------- launch ----------------
extern "C" void kernel_launch(void* const* d_in, const int* in_sizes, int n_in,
                              void* d_out, int out_size) {
    const float* x      = (const float*)d_in[0];
    const float* h      = (const float*)d_in[1];
    const float* wdtlow = (const float*)d_in[2];
    const float* wdt    = (const float*)d_in[3];
    const float* bdt    = (const float*)d_in[4];
    const float* wb     = (const float*)d_in[5];
    const float* wc     = (const float*)d_in[6];
    const float* alog   = (const float*)d_in[7];
    const float* Dv     = (const float*)d_in[8];
    float* y = (float*)d_out;

    prep_a_kernel<<<(DIN * DST + 255) / 256, 256>>>(alog);
    gemm1_kernel<<<dim3(B_SZ / 64, NPROJ / 64, SPLITK), 128>>>(x, wdtlow, wb, wc);
    reduce_kernel<<<(B_SZ * NPROJ / 2 + 255) / 256, 256>>>();
    gemm2_kernel<<<dim3(B_SZ / 128, DIN / 64), 256>>>(wdt, bdt);
    ssm_kernel<<<dim3(DIN / 64, B_SZ), 256>>>(x, h, Dv, y);
}

// round 5
// speedup vs baseline: 1.4095x; 1.3968x over previous
#include <cuda_runtime.h>
#include <cuda_bf16.h>
#include <mma.h>
#include <math.h>
#include <stdint.h>

using namespace nvcuda;

// 0: x [1024,2560]  1: h [1024,2560,16]  2: W_dt_low [160,2560]  3: W_dt [2560,160]
// 4: b_dt [2560]    5: W_B [16,2560]     6: W_C [16,2560]        7: A_log [2560,16]
// 8: D [2560]       out: y [1024,2560]   all f32

#define B_SZ    1024
#define DIN     2560
#define DST     16
#define DTR     160
#define NPROJ   192
#define KPAD    192
#define SPLITK  16
#define KSPLIT  (DIN / SPLITK)   // 160
#define KC      32               // k per smem chunk
#define PADK    48               // padded k-stride in smem (96B rows)

// ---------------- device scratch ----------------
__device__ __align__(16) __nv_bfloat16 g_xh[B_SZ * DIN], g_xl[B_SZ * DIN];
__device__ __align__(16) __nv_bfloat16 g_w1h[NPROJ * DIN], g_w1l[NPROJ * DIN];
__device__ __align__(16) __nv_bfloat16 g_w2h[DIN * KPAD], g_w2l[DIN * KPAD];
__device__ __align__(16) __nv_bfloat16 g_ph[B_SZ * KPAD], g_pl[B_SZ * KPAD];
__device__ __align__(16) float g_partial[SPLITK * B_SZ * NPROJ];
__device__ __align__(16) float g_proj[B_SZ * NPROJ];
__device__ __align__(16) float g_dt[B_SZ * DIN];
__device__ __align__(16) float g_A2[DIN * DST];

// ---------------- hi/lo split ----------------
__device__ __forceinline__ void split2(float v, __nv_bfloat16& hi, __nv_bfloat16& lo) {
    hi = __float2bfloat16(v);
    lo = __float2bfloat16(v - __bfloat162float(hi));
}

// ---------------- conversions ----------------
__global__ void conv_x_kernel(const float* __restrict__ src) {
    int i = blockIdx.x * blockDim.x + threadIdx.x;
    const int n4 = B_SZ * DIN / 4;
    if (i >= n4) return;
    float4 v = reinterpret_cast<const float4*>(src)[i];
    __nv_bfloat16 h0, h1, h2, h3, l0, l1, l2, l3;
    split2(v.x, h0, l0); split2(v.y, h1, l1); split2(v.z, h2, l2); split2(v.w, h3, l3);
    reinterpret_cast<__nv_bfloat162*>(g_xh)[i * 2]     = __nv_bfloat162(h0, h1);
    reinterpret_cast<__nv_bfloat162*>(g_xh)[i * 2 + 1] = __nv_bfloat162(h2, h3);
    reinterpret_cast<__nv_bfloat162*>(g_xl)[i * 2]     = __nv_bfloat162(l0, l1);
    reinterpret_cast<__nv_bfloat162*>(g_xl)[i * 2 + 1] = __nv_bfloat162(l2, l3);
}

__global__ void conv_w1_kernel(const float* __restrict__ wdtlow,
                               const float* __restrict__ wb,
                               const float* __restrict__ wc) {
    int i = blockIdx.x * blockDim.x + threadIdx.x;
    const int n4 = NPROJ * DIN / 4;
    if (i >= n4) return;
    int n = i / (DIN / 4);
    int j = i % (DIN / 4);
    const float* row = (n < DTR) ? wdtlow + (size_t)n * DIN
                     : (n < DTR + DST) ? wb + (size_t)(n - DTR) * DIN
                     : wc + (size_t)(n - DTR - DST) * DIN;
    float4 v = reinterpret_cast<const float4*>(row)[j];
    __nv_bfloat16 h0, h1, h2, h3, l0, l1, l2, l3;
    split2(v.x, h0, l0); split2(v.y, h1, l1); split2(v.z, h2, l2); split2(v.w, h3, l3);
    reinterpret_cast<__nv_bfloat162*>(g_w1h)[i * 2]     = __nv_bfloat162(h0, h1);
    reinterpret_cast<__nv_bfloat162*>(g_w1h)[i * 2 + 1] = __nv_bfloat162(h2, h3);
    reinterpret_cast<__nv_bfloat162*>(g_w1l)[i * 2]     = __nv_bfloat162(l0, l1);
    reinterpret_cast<__nv_bfloat162*>(g_w1l)[i * 2 + 1] = __nv_bfloat162(l2, l3);
}

__global__ void conv_w2_kernel(const float* __restrict__ wdt) {
    int i = blockIdx.x * blockDim.x + threadIdx.x;
    if (i >= DIN * KPAD) return;
    int n = i / KPAD, c = i % KPAD;
    float v = (c < DTR) ? wdt[(size_t)n * DTR + c] : 0.f;
    __nv_bfloat16 hi, lo;
    split2(v, hi, lo);
    g_w2h[i] = hi; g_w2l[i] = lo;
}

__global__ void prep_a_kernel(const float* __restrict__ a_log) {
    int i = blockIdx.x * blockDim.x + threadIdx.x;
    if (i < DIN * DST) g_A2[i] = -__expf(a_log[i]);
}

// ---------------- wmma GEMM ----------------
// C[m,n] = sum_k A[m,k]*B[n,k], A/B split hi+lo (3 cross terms), fp32 accum.
// CTA: 128m x 64n, 8 warps in 4x2 grid, each warp 32m x 32n = 2x2 wmma frags.
// MODE 0: A=x[1024,2560], B=W1[192,2560], split-K -> g_partial
// MODE 1: A=proj[1024,192], B=W2[2560,192]      -> softplus -> g_dt
#define SMEM_BYTES 36864

template<int MODE>
__global__ __launch_bounds__(256) void gemm_wmma(const float* __restrict__ bias) {
    __shared__ __align__(16) char smbuf[SMEM_BYTES];
    __nv_bfloat16* sAh = reinterpret_cast<__nv_bfloat16*>(smbuf);            // 128*48*2 = 12288B
    __nv_bfloat16* sAl = reinterpret_cast<__nv_bfloat16*>(smbuf + 12288);
    __nv_bfloat16* sBh = reinterpret_cast<__nv_bfloat16*>(smbuf + 24576);    // 64*48*2 = 6144B
    __nv_bfloat16* sBl = reinterpret_cast<__nv_bfloat16*>(smbuf + 30720);

    const int tid = threadIdx.x;
    const int wid = tid >> 5;
    const int wm = wid >> 1;         // 0..3 -> 32m each
    const int wn = wid & 1;          // 0..1 -> 32n each
    const int mBase = blockIdx.x * 128;
    const int nBase = blockIdx.y * 64;
    const int kOff  = (MODE == 0) ? blockIdx.z * KSPLIT : 0;
    const int ktot  = (MODE == 0) ? KSPLIT : KPAD;
    const int lda   = (MODE == 0) ? DIN : KPAD;
    const int ldb   = (MODE == 0) ? DIN : KPAD;
    const __nv_bfloat16* aH = (MODE == 0) ? g_xh : g_ph;
    const __nv_bfloat16* aL = (MODE == 0) ? g_xl : g_pl;
    const __nv_bfloat16* bH = (MODE == 0) ? g_w1h : g_w2h;
    const __nv_bfloat16* bL = (MODE == 0) ? g_w1l : g_w2l;

    wmma::fragment<wmma::accumulator, 16, 16, 16, float> acc[2][2];
#pragma unroll
    for (int i = 0; i < 2; i++)
#pragma unroll
        for (int j = 0; j < 2; j++) wmma::fill_fragment(acc[i][j], 0.0f);

    for (int k0 = kOff; k0 < kOff + ktot; k0 += KC) {
        // load A: 128 rows x 32 cols (hi+lo) -> 512 uint4 each, 2 per thread
#pragma unroll
        for (int s = 0; s < 2; s++) {
            int u = tid + s * 256;
            int row = u >> 2, c16 = u & 3;        // c16: 16B unit = 8 bf16
            const size_t go = (size_t)(mBase + row) * lda + k0 + c16 * 8;
            *reinterpret_cast<uint4*>(sAh + row * PADK + c16 * 8) =
                *reinterpret_cast<const uint4*>(aH + go);
            *reinterpret_cast<uint4*>(sAl + row * PADK + c16 * 8) =
                *reinterpret_cast<const uint4*>(aL + go);
        }
        // load B: 64 rows x 32 cols (hi+lo) -> 256 uint4 each, 1 per thread
        {
            int row = tid >> 2, c16 = tid & 3;
            const size_t go = (size_t)(nBase + row) * ldb + k0 + c16 * 8;
            *reinterpret_cast<uint4*>(sBh + row * PADK + c16 * 8) =
                *reinterpret_cast<const uint4*>(bH + go);
            *reinterpret_cast<uint4*>(sBl + row * PADK + c16 * 8) =
                *reinterpret_cast<const uint4*>(bL + go);
        }
        __syncthreads();

#pragma unroll
        for (int kk = 0; kk < 2; kk++) {
            wmma::fragment<wmma::matrix_a, 16, 16, 16, __nv_bfloat16, wmma::row_major> ah[2], al[2];
            wmma::fragment<wmma::matrix_b, 16, 16, 16, __nv_bfloat16, wmma::col_major> bh[2], bl[2];
#pragma unroll
            for (int i = 0; i < 2; i++) {
                const __nv_bfloat16* pa = sAh + (wm * 32 + i * 16) * PADK + kk * 16;
                const __nv_bfloat16* pl = sAl + (wm * 32 + i * 16) * PADK + kk * 16;
                wmma::load_matrix_sync(ah[i], pa, PADK);
                wmma::load_matrix_sync(al[i], pl, PADK);
            }
#pragma unroll
            for (int j = 0; j < 2; j++) {
                const __nv_bfloat16* pb = sBh + (wn * 32 + j * 16) * PADK + kk * 16;
                const __nv_bfloat16* pl = sBl + (wn * 32 + j * 16) * PADK + kk * 16;
                wmma::load_matrix_sync(bh[j], pb, PADK);
                wmma::load_matrix_sync(bl[j], pl, PADK);
            }
#pragma unroll
            for (int i = 0; i < 2; i++)
#pragma unroll
                for (int j = 0; j < 2; j++) {
                    wmma::mma_sync(acc[i][j], ah[i], bh[j], acc[i][j]);
                    wmma::mma_sync(acc[i][j], ah[i], bl[j], acc[i][j]);
                    wmma::mma_sync(acc[i][j], al[i], bh[j], acc[i][j]);
                }
        }
        __syncthreads();
    }

    if (MODE == 0) {
        // direct store to g_partial
        float* base = g_partial + ((size_t)blockIdx.z * B_SZ + mBase) * NPROJ + nBase;
#pragma unroll
        for (int i = 0; i < 2; i++)
#pragma unroll
            for (int j = 0; j < 2; j++) {
                float* p = base + (size_t)(wm * 32 + i * 16) * NPROJ + wn * 32 + j * 16;
                wmma::store_matrix_sync(p, acc[i][j], NPROJ, wmma::mem_row_major);
            }
    } else {
        // stage to smem, then softplus + write
        float* stage = reinterpret_cast<float*>(smbuf);   // 128 x 68 floats = 34816B
#pragma unroll
        for (int i = 0; i < 2; i++)
#pragma unroll
            for (int j = 0; j < 2; j++) {
                float* p = stage + (size_t)(wm * 32 + i * 16) * 68 + wn * 32 + j * 16;
                wmma::store_matrix_sync(p, acc[i][j], 68, wmma::mem_row_major);
            }
        __syncthreads();
        // 128 rows x 16 float4 per row = 2048 float4; 256 thr -> 8 each
#pragma unroll
        for (int s = 0; s < 8; s++) {
            int u = tid + s * 256;
            int row = u >> 4, c4 = (u & 15) * 4;
            float4 v = *reinterpret_cast<float4*>(stage + row * 68 + c4);
            const int gn = nBase + c4;
            v.x += __ldg(bias + gn);     v.y += __ldg(bias + gn + 1);
            v.z += __ldg(bias + gn + 2); v.w += __ldg(bias + gn + 3);
            float4 o;
            o.x = fmaxf(v.x, 0.f) + log1pf(__expf(-fabsf(v.x)));
            o.y = fmaxf(v.y, 0.f) + log1pf(__expf(-fabsf(v.y)));
            o.z = fmaxf(v.z, 0.f) + log1pf(__expf(-fabsf(v.z)));
            o.w = fmaxf(v.w, 0.f) + log1pf(__expf(-fabsf(v.w)));
            *reinterpret_cast<float4*>(g_dt + (size_t)(mBase + row) * DIN + gn) = o;
        }
    }
}

// ---------------- split-K reduce + bf16 split of proj ----------------
__global__ void reduce_kernel() {
    int i = blockIdx.x * blockDim.x + threadIdx.x;
    const int total = B_SZ * NPROJ;
    if (i >= total) return;
    float s = g_partial[i];
#pragma unroll
    for (int z = 1; z < SPLITK; z++) s += g_partial[(size_t)z * total + i];
    g_proj[i] = s;
    __nv_bfloat16 hi, lo;
    split2(s, hi, lo);
    g_ph[i] = hi; g_pl[i] = lo;
}

// ---------------- elementwise SSM ----------------
__global__ __launch_bounds__(256) void ssm_kernel(const float* __restrict__ x,
                                                  const float* __restrict__ h,
                                                  const float* __restrict__ Dv,
                                                  float* __restrict__ y) {
    __shared__ float ys[64];
    const int b = blockIdx.y;
    const int dBase = blockIdx.x * 64;
    const int tid = threadIdx.x;
    const int l4 = tid & 3;
    const int d = dBase + (tid >> 2);
    const int pair = b * DIN + d;

    const float dt_v = g_dt[pair];
    const float x_v = x[pair];
    const float4 h4  = *reinterpret_cast<const float4*>(h + (size_t)pair * DST + l4 * 4);
    const float4 A4  = *reinterpret_cast<const float4*>(g_A2 + (size_t)d * DST + l4 * 4);
    const float4 Bt4 = *reinterpret_cast<const float4*>(g_proj + (size_t)b * NPROJ + DTR + l4 * 4);
    const float4 Ct4 = *reinterpret_cast<const float4*>(g_proj + (size_t)b * NPROJ + DTR + DST + l4 * 4);

    const float dx = dt_v * x_v;
    float acc;
    {
        float e0 = __expf(dt_v * A4.x);
        float e1 = __expf(dt_v * A4.y);
        float e2 = __expf(dt_v * A4.z);
        float e3 = __expf(dt_v * A4.w);
        float hn0 = fmaf(e0, h4.x, dx * Bt4.x);
        float hn1 = fmaf(e1, h4.y, dx * Bt4.y);
        float hn2 = fmaf(e2, h4.z, dx * Bt4.z);
        float hn3 = fmaf(e3, h4.w, dx * Bt4.w);
        acc = hn0 * Ct4.x;
        acc = fmaf(hn1, Ct4.y, acc);
        acc = fmaf(hn2, Ct4.z, acc);
        acc = fmaf(hn3, Ct4.w, acc);
    }
    acc += __shfl_xor_sync(0xffffffffu, acc, 1);
    acc += __shfl_xor_sync(0xffffffffu, acc, 2);
    if (l4 == 0) ys[tid >> 2] = fmaf(Dv[d], x_v, acc);
    __syncthreads();
    if (tid < 64) y[(size_t)b * DIN + dBase + tid] = ys[tid];
}

// ---------------- launch ----------------
extern "C" void kernel_launch(void* const* d_in, const int* in_sizes, int n_in,
                              void* d_out, int out_size) {
    const float* x      = (const float*)d_in[0];
    const float* h      = (const float*)d_in[1];
    const float* wdtlow = (const float*)d_in[2];
    const float* wdt    = (const float*)d_in[3];
    const float* bdt    = (const float*)d_in[4];
    const float* wb     = (const float*)d_in[5];
    const float* wc     = (const float*)d_in[6];
    const float* alog   = (const float*)d_in[7];
    const float* Dv     = (const float*)d_in[8];
    float* y = (float*)d_out;

    conv_x_kernel<<<(B_SZ * DIN / 4 + 255) / 256, 256>>>(x);
    conv_w1_kernel<<<(NPROJ * DIN / 4 + 255) / 256, 256>>>(wdtlow, wb, wc);
    conv_w2_kernel<<<(DIN * KPAD + 255) / 256, 256>>>(wdt);
    prep_a_kernel<<<(DIN * DST + 255) / 256, 256>>>(alog);

    gemm_wmma<0><<<dim3(B_SZ / 128, NPROJ / 64, SPLITK), 256>>>(bdt);
    reduce_kernel<<<(B_SZ * NPROJ + 255) / 256, 256>>>();
    gemm_wmma<1><<<dim3(B_SZ / 128, DIN / 64, 1), 256>>>(bdt);
    ssm_kernel<<<dim3(DIN / 64, B_SZ), 256>>>(x, h, Dv, y);
}

// round 6
// speedup vs baseline: 1.5890x; 1.1274x over previous
#include <cuda_runtime.h>
#include <cuda_bf16.h>
#include <mma.h>
#include <math.h>
#include <stdint.h>

using namespace nvcuda;

// 0: x [1024,2560]  1: h [1024,2560,16]  2: W_dt_low [160,2560]  3: W_dt [2560,160]
// 4: b_dt [2560]    5: W_B [16,2560]     6: W_C [16,2560]        7: A_log [2560,16]
// 8: D [2560]       out: y [1024,2560]   all f32

#define B_SZ    1024
#define DIN     2560
#define DST     16
#define DTR     160
#define NPROJ   192
#define KPAD    192
#define SPLITK  8
#define KSPLIT  (DIN / SPLITK)   // 320
#define KC      32               // k per smem chunk
#define PADK    40               // padded k-stride in smem (80B rows, mult of 8 elems)

// ---------------- device scratch ----------------
__device__ __align__(16) __nv_bfloat16 g_xh[B_SZ * DIN], g_xl[B_SZ * DIN];
__device__ __align__(16) __nv_bfloat16 g_w1h[NPROJ * DIN], g_w1l[NPROJ * DIN];
__device__ __align__(16) __nv_bfloat16 g_w2h[DIN * KPAD], g_w2l[DIN * KPAD];
__device__ __align__(16) __nv_bfloat16 g_ph[B_SZ * KPAD], g_pl[B_SZ * KPAD];
__device__ __align__(16) float g_partial[SPLITK * B_SZ * NPROJ];
__device__ __align__(16) float g_proj[B_SZ * NPROJ];
__device__ __align__(16) float g_dt[B_SZ * DIN];
__device__ __align__(16) float g_A2[DIN * DST];

// ---------------- helpers ----------------
__device__ __forceinline__ void split2(float v, __nv_bfloat16& hi, __nv_bfloat16& lo) {
    hi = __float2bfloat16(v);
    lo = __float2bfloat16(v - __bfloat162float(hi));
}
__device__ __forceinline__ void split_store4(float4 v, __nv_bfloat16* ph, __nv_bfloat16* pl) {
    __nv_bfloat16 h0, h1, h2, h3, l0, l1, l2, l3;
    split2(v.x, h0, l0); split2(v.y, h1, l1); split2(v.z, h2, l2); split2(v.w, h3, l3);
    reinterpret_cast<__nv_bfloat162*>(ph)[0] = __nv_bfloat162(h0, h1);
    reinterpret_cast<__nv_bfloat162*>(ph)[1] = __nv_bfloat162(h2, h3);
    reinterpret_cast<__nv_bfloat162*>(pl)[0] = __nv_bfloat162(l0, l1);
    reinterpret_cast<__nv_bfloat162*>(pl)[1] = __nv_bfloat162(l2, l3);
}
__device__ __forceinline__ void cp16(void* sdst, const void* gsrc) {
    asm volatile("cp.async.cg.shared.global [%0], [%1], 16;"
        :: "r"((uint32_t)__cvta_generic_to_shared(sdst)), "l"(gsrc));
}
#define CP_COMMIT() asm volatile("cp.async.commit_group;" ::: "memory")
#define CP_WAIT(N)  asm volatile("cp.async.wait_group %0;" :: "n"(N) : "memory")

// ---------------- fused prep: conv_x | conv_w1 | conv_w2 | prep_a ----------------
// task block ranges: [0,2560) conv_x; [2560,3040) conv_w1; [3040,3520) conv_w2; [3520,3560) prep_a
#define PREP_BLOCKS 3560
__global__ __launch_bounds__(256) void prep_all(const float* __restrict__ x,
                                                const float* __restrict__ wdtlow,
                                                const float* __restrict__ wb,
                                                const float* __restrict__ wc,
                                                const float* __restrict__ wdt,
                                                const float* __restrict__ alog) {
    const int bid = blockIdx.x;
    const int tid = threadIdx.x;
    if (bid < 2560) {
        // conv_x: 655360 float4
        int i = bid * 256 + tid;
        float4 v = reinterpret_cast<const float4*>(x)[i];
        split_store4(v, g_xh + i * 4, g_xl + i * 4);
    } else if (bid < 3040) {
        // conv_w1: 122880 float4
        int i = (bid - 2560) * 256 + tid;
        int n = i / (DIN / 4);
        int j = i % (DIN / 4);
        const float* row = (n < DTR) ? wdtlow + (size_t)n * DIN
                         : (n < DTR + DST) ? wb + (size_t)(n - DTR) * DIN
                         : wc + (size_t)(n - DTR - DST) * DIN;
        float4 v = reinterpret_cast<const float4*>(row)[j];
        split_store4(v, g_w1h + i * 4, g_w1l + i * 4);
    } else if (bid < 3520) {
        // conv_w2: 122880 float4-granules over [DIN, KPAD], zero pad c>=DTR
        int i = (bid - 3040) * 256 + tid;
        int n = i / (KPAD / 4);
        int c4 = (i % (KPAD / 4)) * 4;
        float4 v = (c4 < DTR) ? *reinterpret_cast<const float4*>(wdt + (size_t)n * DTR + c4)
                              : make_float4(0.f, 0.f, 0.f, 0.f);
        split_store4(v, g_w2h + (size_t)n * KPAD + c4, g_w2l + (size_t)n * KPAD + c4);
    } else {
        // prep_a: 10240 float4
        int i = (bid - 3520) * 256 + tid;
        float4 v = reinterpret_cast<const float4*>(alog)[i];
        float4 o = make_float4(-__expf(v.x), -__expf(v.y), -__expf(v.z), -__expf(v.w));
        reinterpret_cast<float4*>(g_A2)[i] = o;
    }
}

// ---------------- wmma GEMM with cp.async 2-stage pipeline ----------------
// CTA: 128m x 64n, 8 warps (4x2), each 32m x 32n = 2x2 frags; 3-term hi/lo split.
// MODE 0: A=x, B=W1, split-K -> g_partial.  MODE 1: A=proj, B=W2 -> softplus -> g_dt.
// dyn smem/stage: sAh 10240 | sAl 10240 | sBh 5120 | sBl 5120 = 30720; x2 = 61440
#define STAGE_SZ 30720
#define SMEM_DYN (2 * STAGE_SZ)

template<int MODE>
__global__ __launch_bounds__(256) void gemm_wmma(const float* __restrict__ bias) {
    extern __shared__ __align__(16) char smbuf[];
    const int tid = threadIdx.x;
    const int wid = tid >> 5;
    const int wm = wid >> 1;
    const int wn = wid & 1;
    const int mBase = blockIdx.x * 128;
    const int nBase = blockIdx.y * 64;
    const int kOff  = (MODE == 0) ? blockIdx.z * KSPLIT : 0;
    const int nch   = ((MODE == 0) ? KSPLIT : KPAD) / KC;
    const int lda   = (MODE == 0) ? DIN : KPAD;
    const int ldb   = (MODE == 0) ? DIN : KPAD;
    const __nv_bfloat16* aH = (MODE == 0) ? g_xh : g_ph;
    const __nv_bfloat16* aL = (MODE == 0) ? g_xl : g_pl;
    const __nv_bfloat16* bH = (MODE == 0) ? g_w1h : g_w2h;
    const __nv_bfloat16* bL = (MODE == 0) ? g_w1l : g_w2l;

    // per-thread load slots
    const int arow = tid >> 1;            // 0..127 (2 chunks per row pair)... see below
    // A: 128 rows x 4 chunks(16B) x2(hi/lo) = 1024 cp16; 256 thr -> 4 each
    // B: 64 rows x 4 chunks x2 = 512; -> 2 each
    (void)arow;

    auto prefetch = [&](int stage, int k0) {
        char* base = smbuf + stage * STAGE_SZ;
        __nv_bfloat16* sAh = reinterpret_cast<__nv_bfloat16*>(base);
        __nv_bfloat16* sAl = reinterpret_cast<__nv_bfloat16*>(base + 10240);
        __nv_bfloat16* sBh = reinterpret_cast<__nv_bfloat16*>(base + 20480);
        __nv_bfloat16* sBl = reinterpret_cast<__nv_bfloat16*>(base + 25600);
#pragma unroll
        for (int s = 0; s < 2; s++) {
            int u = tid + s * 256;        // 0..511 : row = u>>2, chunk = u&3
            int row = u >> 2, c16 = u & 3;
            const size_t go = (size_t)(mBase + row) * lda + k0 + c16 * 8;
            cp16(sAh + row * PADK + c16 * 8, aH + go);
            cp16(sAl + row * PADK + c16 * 8, aL + go);
        }
        {
            int row = tid >> 2, c16 = tid & 3;
            const size_t go = (size_t)(nBase + row) * ldb + k0 + c16 * 8;
            cp16(sBh + row * PADK + c16 * 8, bH + go);
            cp16(sBl + row * PADK + c16 * 8, bL + go);
        }
        CP_COMMIT();
    };

    wmma::fragment<wmma::accumulator, 16, 16, 16, float> acc[2][2];
#pragma unroll
    for (int i = 0; i < 2; i++)
#pragma unroll
        for (int j = 0; j < 2; j++) wmma::fill_fragment(acc[i][j], 0.0f);

    prefetch(0, kOff);

    for (int ch = 0; ch < nch; ch++) {
        const int stage = ch & 1;
        if (ch + 1 < nch) {
            prefetch(stage ^ 1, kOff + (ch + 1) * KC);
            CP_WAIT(1);
        } else {
            CP_WAIT(0);
        }
        __syncthreads();

        char* base = smbuf + stage * STAGE_SZ;
        __nv_bfloat16* sAh = reinterpret_cast<__nv_bfloat16*>(base);
        __nv_bfloat16* sAl = reinterpret_cast<__nv_bfloat16*>(base + 10240);
        __nv_bfloat16* sBh = reinterpret_cast<__nv_bfloat16*>(base + 20480);
        __nv_bfloat16* sBl = reinterpret_cast<__nv_bfloat16*>(base + 25600);

#pragma unroll
        for (int kk = 0; kk < 2; kk++) {
            wmma::fragment<wmma::matrix_a, 16, 16, 16, __nv_bfloat16, wmma::row_major> ah[2], al[2];
            wmma::fragment<wmma::matrix_b, 16, 16, 16, __nv_bfloat16, wmma::col_major> bh[2], bl[2];
#pragma unroll
            for (int i = 0; i < 2; i++) {
                wmma::load_matrix_sync(ah[i], sAh + (wm * 32 + i * 16) * PADK + kk * 16, PADK);
                wmma::load_matrix_sync(al[i], sAl + (wm * 32 + i * 16) * PADK + kk * 16, PADK);
            }
#pragma unroll
            for (int j = 0; j < 2; j++) {
                wmma::load_matrix_sync(bh[j], sBh + (wn * 32 + j * 16) * PADK + kk * 16, PADK);
                wmma::load_matrix_sync(bl[j], sBl + (wn * 32 + j * 16) * PADK + kk * 16, PADK);
            }
#pragma unroll
            for (int i = 0; i < 2; i++)
#pragma unroll
                for (int j = 0; j < 2; j++) {
                    wmma::mma_sync(acc[i][j], ah[i], bh[j], acc[i][j]);
                    wmma::mma_sync(acc[i][j], ah[i], bl[j], acc[i][j]);
                    wmma::mma_sync(acc[i][j], al[i], bh[j], acc[i][j]);
                }
        }
        __syncthreads();
    }

    if (MODE == 0) {
        float* base = g_partial + ((size_t)blockIdx.z * B_SZ + mBase) * NPROJ + nBase;
#pragma unroll
        for (int i = 0; i < 2; i++)
#pragma unroll
            for (int j = 0; j < 2; j++) {
                float* p = base + (size_t)(wm * 32 + i * 16) * NPROJ + wn * 32 + j * 16;
                wmma::store_matrix_sync(p, acc[i][j], NPROJ, wmma::mem_row_major);
            }
    } else {
        float* stage = reinterpret_cast<float*>(smbuf);   // 128 x 68 f32 = 34816B < SMEM_DYN
#pragma unroll
        for (int i = 0; i < 2; i++)
#pragma unroll
            for (int j = 0; j < 2; j++) {
                float* p = stage + (size_t)(wm * 32 + i * 16) * 68 + wn * 32 + j * 16;
                wmma::store_matrix_sync(p, acc[i][j], 68, wmma::mem_row_major);
            }
        __syncthreads();
#pragma unroll
        for (int s = 0; s < 8; s++) {
            int u = tid + s * 256;
            int row = u >> 4, c4 = (u & 15) * 4;
            float4 v = *reinterpret_cast<float4*>(stage + row * 68 + c4);
            const int gn = nBase + c4;
            v.x += __ldg(bias + gn);     v.y += __ldg(bias + gn + 1);
            v.z += __ldg(bias + gn + 2); v.w += __ldg(bias + gn + 3);
            float4 o;
            o.x = fmaxf(v.x, 0.f) + log1pf(__expf(-fabsf(v.x)));
            o.y = fmaxf(v.y, 0.f) + log1pf(__expf(-fabsf(v.y)));
            o.z = fmaxf(v.z, 0.f) + log1pf(__expf(-fabsf(v.z)));
            o.w = fmaxf(v.w, 0.f) + log1pf(__expf(-fabsf(v.w)));
            *reinterpret_cast<float4*>(g_dt + (size_t)(mBase + row) * DIN + gn) = o;
        }
    }
}

// ---------------- split-K reduce + bf16 split of proj ----------------
__global__ void reduce_kernel() {
    int i = blockIdx.x * blockDim.x + threadIdx.x;
    const int total = B_SZ * NPROJ;
    if (i >= total) return;
    float s = g_partial[i];
#pragma unroll
    for (int z = 1; z < SPLITK; z++) s += g_partial[(size_t)z * total + i];
    g_proj[i] = s;
    __nv_bfloat16 hi, lo;
    split2(s, hi, lo);
    g_ph[i] = hi; g_pl[i] = lo;
}

// ---------------- elementwise SSM ----------------
__global__ __launch_bounds__(256) void ssm_kernel(const float* __restrict__ x,
                                                  const float* __restrict__ h,
                                                  const float* __restrict__ Dv,
                                                  float* __restrict__ y) {
    __shared__ float ys[64];
    const int b = blockIdx.y;
    const int dBase = blockIdx.x * 64;
    const int tid = threadIdx.x;
    const int l4 = tid & 3;
    const int d = dBase + (tid >> 2);
    const int pair = b * DIN + d;

    const float dt_v = g_dt[pair];
    const float x_v = x[pair];
    const float4 h4  = *reinterpret_cast<const float4*>(h + (size_t)pair * DST + l4 * 4);
    const float4 A4  = *reinterpret_cast<const float4*>(g_A2 + (size_t)d * DST + l4 * 4);
    const float4 Bt4 = *reinterpret_cast<const float4*>(g_proj + (size_t)b * NPROJ + DTR + l4 * 4);
    const float4 Ct4 = *reinterpret_cast<const float4*>(g_proj + (size_t)b * NPROJ + DTR + DST + l4 * 4);

    const float dx = dt_v * x_v;
    float acc;
    {
        float e0 = __expf(dt_v * A4.x);
        float e1 = __expf(dt_v * A4.y);
        float e2 = __expf(dt_v * A4.z);
        float e3 = __expf(dt_v * A4.w);
        float hn0 = fmaf(e0, h4.x, dx * Bt4.x);
        float hn1 = fmaf(e1, h4.y, dx * Bt4.y);
        float hn2 = fmaf(e2, h4.z, dx * Bt4.z);
        float hn3 = fmaf(e3, h4.w, dx * Bt4.w);
        acc = hn0 * Ct4.x;
        acc = fmaf(hn1, Ct4.y, acc);
        acc = fmaf(hn2, Ct4.z, acc);
        acc = fmaf(hn3, Ct4.w, acc);
    }
    acc += __shfl_xor_sync(0xffffffffu, acc, 1);
    acc += __shfl_xor_sync(0xffffffffu, acc, 2);
    if (l4 == 0) ys[tid >> 2] = fmaf(Dv[d], x_v, acc);
    __syncthreads();
    if (tid < 64) y[(size_t)b * DIN + dBase + tid] = ys[tid];
}

// ---------------- launch ----------------
extern "C" void kernel_launch(void* const* d_in, const int* in_sizes, int n_in,
                              void* d_out, int out_size) {
    const float* x      = (const float*)d_in[0];
    const float* h      = (const float*)d_in[1];
    const float* wdtlow = (const float*)d_in[2];
    const float* wdt    = (const float*)d_in[3];
    const float* bdt    = (const float*)d_in[4];
    const float* wb     = (const float*)d_in[5];
    const float* wc     = (const float*)d_in[6];
    const float* alog   = (const float*)d_in[7];
    const float* Dv     = (const float*)d_in[8];
    float* y = (float*)d_out;

    cudaFuncSetAttribute(gemm_wmma<0>, cudaFuncAttributeMaxDynamicSharedMemorySize, SMEM_DYN);
    cudaFuncSetAttribute(gemm_wmma<1>, cudaFuncAttributeMaxDynamicSharedMemorySize, SMEM_DYN);

    prep_all<<<PREP_BLOCKS, 256>>>(x, wdtlow, wb, wc, wdt, alog);
    gemm_wmma<0><<<dim3(B_SZ / 128, NPROJ / 64, SPLITK), 256, SMEM_DYN>>>(bdt);
    reduce_kernel<<<(B_SZ * NPROJ + 255) / 256, 256>>>();
    gemm_wmma<1><<<dim3(B_SZ / 128, DIN / 64, 1), 256, SMEM_DYN>>>(bdt);
    ssm_kernel<<<dim3(DIN / 64, B_SZ), 256>>>(x, h, Dv, y);
}